// round 16
// baseline (speedup 1.0000x reference)
#include <cuda_runtime.h>

// Problem dims
#define N_   128
#define C_   64
#define T_   288
#define V_   16
#define S_   3
#define IC_  16
#define KCT  (IC_*T_)      // 4608
#define TV_  (T_*V_)       // 4608

// Kernel 1 tiling
#define TT1  8
#define NCH  (T_/TT1)      // 36
#define FS1  196           // k1 fa/fb i-stride (≡ 4 mod 32)
#define FT1  24            // k1 fa/fb tp-stride

// Kernel 3 tiling
#define TT3  8
#define NCH3 (T_/TT3)      // 36
#define RS3  132           // k3 xs row stride (≡ 4 mod 32)

// Scratch (no cudaMalloc allowed)
__device__ float g_partial[(long)N_*NCH*S_*V_*V_];   // [n][ch][s][v*16+w]
__device__ float g_att[(long)N_*S_*V_*V_];           // [n][s][v*16+w]
__device__ uint4 g_Wfrag[S_*4*8*32];                 // Wd tf32 B-frags [s][og][step][lane]
__device__ uint2 g_W1frag[S_*2*2*8*32];              // Wa/Wb tf32 B-frags [s][ab][nt][ks][lane]

typedef unsigned long long u64;

__device__ __forceinline__ u64 splat2(float x) {
    u64 r; asm("mov.b64 %0, {%1, %1};" : "=l"(r) : "f"(x)); return r;
}
__device__ __forceinline__ void fma2(u64& d, u64 a, u64 b) {
    asm("fma.rn.f32x2 %0, %1, %2, %0;" : "+l"(d) : "l"(a), "l"(b));
}
__device__ __forceinline__ u64 add2(u64 a, u64 b) {
    u64 r; asm("add.rn.f32x2 %0, %1, %2;" : "=l"(r) : "l"(a), "l"(b)); return r;
}
__device__ __forceinline__ unsigned cvt_tf32(float f) {
    unsigned r; asm("cvt.rna.tf32.f32 %0, %1;" : "=r"(r) : "f"(f)); return r;
}
__device__ __forceinline__ void mma_tf32(float* d, unsigned a0, unsigned a1,
                                         unsigned a2, unsigned a3,
                                         unsigned b0, unsigned b1) {
    asm("mma.sync.aligned.m16n8k8.row.col.f32.tf32.tf32.f32 "
        "{%0,%1,%2,%3}, {%4,%5,%6,%7}, {%8,%9}, {%0,%1,%2,%3};"
        : "+f"(d[0]), "+f"(d[1]), "+f"(d[2]), "+f"(d[3])
        : "r"(a0), "r"(a1), "r"(a2), "r"(a3), "r"(b0), "r"(b1));
}

// ---------------------------------------------------------------------------
// Kernel 0: pre-pack Wd and Wa/Wb into tf32 mma B-fragments.
// ---------------------------------------------------------------------------
extern "C" __global__ void k0_prep(const float* __restrict__ Wa,
                                   const float* __restrict__ Wb,
                                   const float* __restrict__ Wd)
{
    const int tid = threadIdx.x;
    for (int idx = tid; idx < S_*4*8*32; idx += 256) {
        int lane = idx & 31, step = (idx >> 5) & 7, og = (idx >> 8) & 3, s = idx >> 10;
        int o = og*16 + (lane >> 2);
        int c = step*8 + (lane & 3);
        uint4 v;
        v.x = cvt_tf32(Wd[(s*64 + o    )*64 + c    ]);
        v.y = cvt_tf32(Wd[(s*64 + o    )*64 + c + 4]);
        v.z = cvt_tf32(Wd[(s*64 + o + 8)*64 + c    ]);
        v.w = cvt_tf32(Wd[(s*64 + o + 8)*64 + c + 4]);
        g_Wfrag[idx] = v;
    }
    for (int idx = tid; idx < S_*2*2*8*32; idx += 256) {
        int lane = idx & 31, ks = (idx >> 5) & 7, nt = (idx >> 8) & 1,
            ab = (idx >> 9) & 1, s = idx >> 10;
        int i = nt*8 + (lane >> 2);
        int c = ks*8 + (lane & 3);
        const float* W = ab ? Wb : Wa;
        uint2 v;
        v.x = cvt_tf32(W[(s*16 + i)*64 + c    ]);
        v.y = cvt_tf32(W[(s*16 + i)*64 + c + 4]);
        g_W1frag[idx] = v;
    }
}

// ---------------------------------------------------------------------------
// Kernel 1: att logit partials, tf32 mma. Grid (NCH, N), 256 threads, occ 4.
// A-fragments loaded directly from global x (hoisted across all 3 s).
// ---------------------------------------------------------------------------
#define SM1_FA   0
#define SM1_FB   (16*FS1)                    // 3136
#define SM1_ATTP (32*FS1)                    // 6272
#define SMEM1_BYTES ((32*FS1 + 8*256)*4)     // 33280 B

extern "C" __global__ void __launch_bounds__(256, 4)
k1_att_partial(const float* __restrict__ x,
               const float* __restrict__ ba, const float* __restrict__ bb)
{
    extern __shared__ float sm[];
    unsigned* fau = (unsigned*)(sm + SM1_FA);
    unsigned* fbu = (unsigned*)(sm + SM1_FB);
    float* attp = sm + SM1_ATTP;                // [8][256]

    const int ch  = blockIdx.x;
    const int n   = blockIdx.y;
    const int tid = threadIdx.x;
    const int lane = tid & 31, wrp = tid >> 5;
    const int lg = lane >> 2, l4 = lane & 3;
    const int j0p1 = wrp * 16;

    const long xbase = (long)n*C_*TV_ + (long)(ch*TT1)*V_;
    const float* xg = x + xbase;

    // Hoisted phase-1 A-frags: a = x[(ks*8 + l4 (+4))*TV + j0p1 + lg (+8)]
    unsigned af[8][4];
    #pragma unroll
    for (int ks = 0; ks < 8; ks++) {
        const float* r0p = &xg[(long)(ks*8 + l4    )*TV_ + j0p1 + lg];
        const float* r1p = &xg[(long)(ks*8 + l4 + 4)*TV_ + j0p1 + lg];
        af[ks][0] = cvt_tf32(__ldg(r0p));
        af[ks][1] = cvt_tf32(__ldg(r0p + 8));
        af[ks][2] = cvt_tf32(__ldg(r1p));
        af[ks][3] = cvt_tf32(__ldg(r1p + 8));
    }

    for (int s = 0; s < S_; s++) {
        // ---- phase 1: fa^T/fb^T via mma; warp owns j-tile [wrp*16, +16) ----
        {
            float dA[2][4], dB[2][4];
            #pragma unroll
            for (int nt = 0; nt < 2; nt++)
                #pragma unroll
                for (int r = 0; r < 4; r++) { dA[nt][r] = 0.f; dB[nt][r] = 0.f; }

            const uint2* wfa = &g_W1frag[((s*2 + 0)*2)*8*32 + lane];
            const uint2* wfb = &g_W1frag[((s*2 + 1)*2)*8*32 + lane];
            #pragma unroll
            for (int ks = 0; ks < 8; ks++) {
                uint2 bA0 = wfa[(0*8 + ks)*32];
                uint2 bA1 = wfa[(1*8 + ks)*32];
                uint2 bB0 = wfb[(0*8 + ks)*32];
                uint2 bB1 = wfb[(1*8 + ks)*32];
                mma_tf32(dA[0], af[ks][0], af[ks][1], af[ks][2], af[ks][3], bA0.x, bA0.y);
                mma_tf32(dA[1], af[ks][0], af[ks][1], af[ks][2], af[ks][3], bA1.x, bA1.y);
                mma_tf32(dB[0], af[ks][0], af[ks][1], af[ks][2], af[ks][3], bB0.x, bB0.y);
                mma_tf32(dB[1], af[ks][0], af[ks][1], af[ks][2], af[ks][3], bB1.x, bB1.y);
            }
            #pragma unroll
            for (int nt = 0; nt < 2; nt++) {
                int ii0 = nt*8 + 2*l4;
                float ba0 = __ldg(&ba[s*16 + ii0]), ba1 = __ldg(&ba[s*16 + ii0 + 1]);
                float bb0 = __ldg(&bb[s*16 + ii0]), bb1 = __ldg(&bb[s*16 + ii0 + 1]);
                int base0 =  ii0     *FS1 + wrp*FT1;
                int base1 = (ii0 + 1)*FS1 + wrp*FT1;
                fau[base0 + lg    ] = cvt_tf32(dA[nt][0] + ba0);
                fau[base1 + lg    ] = cvt_tf32(dA[nt][1] + ba1);
                fau[base0 + lg + 8] = cvt_tf32(dA[nt][2] + ba0);
                fau[base1 + lg + 8] = cvt_tf32(dA[nt][3] + ba1);
                fbu[base0 + lg    ] = cvt_tf32(dB[nt][0] + bb0);
                fbu[base1 + lg    ] = cvt_tf32(dB[nt][1] + bb1);
                fbu[base0 + lg + 8] = cvt_tf32(dB[nt][2] + bb0);
                fbu[base1 + lg + 8] = cvt_tf32(dB[nt][3] + bb1);
            }
        }
        __syncthreads();

        // ---- phase 2: att[v,w] partials via mma; warp owns i in {2w, 2w+1} ----
        {
            float p[2][4];
            #pragma unroll
            for (int nt = 0; nt < 2; nt++)
                #pragma unroll
                for (int r = 0; r < 4; r++) p[nt][r] = 0.f;

            #pragma unroll
            for (int t = 0; t < 2; t++) {
                int kk = wrp*2 + t;
                int ab = kk*FS1 + l4*FT1;
                unsigned a0 = fau[ab                  + lg    ];
                unsigned a1 = fau[ab                  + lg + 8];
                unsigned a2 = fau[kk*FS1 + (l4+4)*FT1 + lg    ];
                unsigned a3 = fau[kk*FS1 + (l4+4)*FT1 + lg + 8];
                #pragma unroll
                for (int nt = 0; nt < 2; nt++) {
                    unsigned b0 = fbu[ab                  + nt*8 + lg];
                    unsigned b1 = fbu[kk*FS1 + (l4+4)*FT1 + nt*8 + lg];
                    mma_tf32(p[nt], a0, a1, a2, a3, b0, b1);
                }
            }
            float* ap = &attp[wrp*256];
            #pragma unroll
            for (int nt = 0; nt < 2; nt++) {
                int w0 = nt*8 + 2*l4;
                ap[ lg     *16 + w0    ] = p[nt][0];
                ap[ lg     *16 + w0 + 1] = p[nt][1];
                ap[(lg + 8)*16 + w0    ] = p[nt][2];
                ap[(lg + 8)*16 + w0 + 1] = p[nt][3];
            }
        }
        __syncthreads();

        float red = 0.f;
        #pragma unroll
        for (int w = 0; w < 8; w++) red += attp[w*256 + tid];
        g_partial[(((long)n*NCH + ch)*S_ + s)*256 + tid] = red;
    }
}

// ---------------------------------------------------------------------------
// Kernel 2: reduce chunks, /K, softmax over v, + (A_base + PA).
// ---------------------------------------------------------------------------
extern "C" __global__ void k2_softmax(const float* __restrict__ Abase,
                                      const float* __restrict__ PA)
{
    const int b = blockIdx.x;          // n*3 + s
    const int n = b / S_, s = b % S_;
    const int tid = threadIdx.x;       // v*16 + w
    const int w = tid & 15;

    __shared__ float sv[256];
    __shared__ float se[256];

    float sum = 0.f;
    const float* p = &g_partial[((long)n*NCH)*S_*256 + s*256 + tid];
    for (int chv = 0; chv < NCH; chv++) sum += p[(long)chv * (S_*256)];
    float val = sum * (1.0f / (float)KCT);

    sv[tid] = val;
    __syncthreads();
    float m = -1e30f;
    #pragma unroll
    for (int vv = 0; vv < 16; vv++) m = fmaxf(m, sv[vv*16 + w]);
    float e = expf(val - m);
    se[tid] = e;
    __syncthreads();
    float ss = 0.f;
    #pragma unroll
    for (int vv = 0; vv < 16; vv++) ss += se[vv*16 + w];

    float a = e / ss + Abase[s*256 + tid] + PA[s*256 + tid];
    g_att[(long)b*256 + tid] = a;
}

// ---------------------------------------------------------------------------
// Kernel 3: fused z^T+y per warp, barrier-free mainloop (R11 mapping),
// occupancy pushed to 4 CTAs/SM (reg cap 64).
// Grid (NCH3, N), 256 threads, smem 36KB.
// ---------------------------------------------------------------------------
#define SM3_ATT  (64*RS3)                     // 8448
#define SMEM3_BYTES ((64*RS3 + S_*256)*4)     // 36864 B

extern "C" __global__ void __launch_bounds__(256, 4)
k3_out(const float* __restrict__ x,
       const float* __restrict__ bd, const float* __restrict__ gamma,
       const float* __restrict__ beta, float* __restrict__ out)
{
    extern __shared__ float sm[];
    unsigned* xsu   = (unsigned*)sm;           // [64][RS3] tf32 bits
    unsigned* attsu = xsu + SM3_ATT;           // [s][v][w] tf32 bits
    float* yout = sm;                          // overlays xs after mainloop

    const int ch  = blockIdx.x;
    const int n   = blockIdx.y;
    const int tid = threadIdx.x;
    const int lane = tid & 31, wrp = tid >> 5;
    const int lg = lane >> 2, l4 = lane & 3;
    const int plg = (lg >> 1) + ((lg & 1) << 2);   // pi(lg)

    const long xbase = (long)n*C_*TV_ + (long)(ch*TT3)*V_;
    for (int idx = tid; idx < 2048; idx += 256) {
        int c = idx >> 5, jp = (idx & 31)*4;
        float4 xv = *(const float4*)&x[xbase + (long)c*TV_ + jp];
        uint4 t;
        t.x = cvt_tf32(xv.x); t.y = cvt_tf32(xv.y);
        t.z = cvt_tf32(xv.z); t.w = cvt_tf32(xv.w);
        *(uint4*)&xsu[c*RS3 + jp] = t;
    }
    for (int idx = tid; idx < S_*256; idx += 256)
        attsu[idx] = cvt_tf32(g_att[(long)n*S_*256 + idx]);
    __syncthreads();

    const int t16 = wrp * 16;    // this warp's j-tile base

    float acc[8][4];             // [o-group of 8][frag]
    #pragma unroll
    for (int g = 0; g < 8; g++)
        #pragma unroll
        for (int r = 0; r < 4; r++) acc[g][r] = 0.f;

    for (int s = 0; s < S_; s++) {
        // att^T A-frags for z^T-mma (K = v, 2 ksteps)
        unsigned aA[2][4];
        const unsigned* ap = attsu + s*256;
        #pragma unroll
        for (int ks = 0; ks < 2; ks++) {
            aA[ks][0] = ap[(ks*8 + l4    )*16 + lg    ];
            aA[ks][1] = ap[(ks*8 + l4    )*16 + lg + 8];
            aA[ks][2] = ap[(ks*8 + l4 + 4)*16 + lg    ];
            aA[ks][3] = ap[(ks*8 + l4 + 4)*16 + lg + 8];
        }
        const uint4* wfp = &g_Wfrag[s*4*256 + lane];
        #pragma unroll
        for (int step = 0; step < 8; step++) {
            // z^T-mma: produces y A-frags for (j-tile t16, c = step*8..+8)
            int xb = (step*8 + plg)*RS3 + t16 + l4;   // conflict-free LDS
            float d[4] = {0.f, 0.f, 0.f, 0.f};
            mma_tf32(d, aA[0][0], aA[0][1], aA[0][2], aA[0][3],
                     xsu[xb], xsu[xb + 4]);
            mma_tf32(d, aA[1][0], aA[1][1], aA[1][2], aA[1][3],
                     xsu[xb + 8], xsu[xb + 12]);
            unsigned y0 = cvt_tf32(d[0]);
            unsigned y1 = cvt_tf32(d[2]);
            unsigned y2 = cvt_tf32(d[1]);
            unsigned y3 = cvt_tf32(d[3]);
            // y-mma across all 4 Wd og-frags (8 n-groups)
            #pragma unroll
            for (int og = 0; og < 4; og++) {
                uint4 bfw = wfp[og*256 + step*32];    // LDG.128, L1-resident
                mma_tf32(acc[og*2    ], y0, y1, y2, y3, bfw.x, bfw.y);
                mma_tf32(acc[og*2 + 1], y0, y1, y2, y3, bfw.z, bfw.w);
            }
        }
    }
    __syncthreads();   // all xs reads done; yout overlays xs

    // ---- scatter y D-frags to yout as [o][130] ----
    #pragma unroll
    for (int g = 0; g < 8; g++) {
        int oc = g*8 + 2*l4;
        int jr = t16 + lg;
        yout[ oc     *130 + jr    ] = acc[g][0];
        yout[(oc + 1)*130 + jr    ] = acc[g][1];
        yout[ oc     *130 + jr + 8] = acc[g][2];
        yout[(oc + 1)*130 + jr + 8] = acc[g][3];
    }
    __syncthreads();

    // ---- epilogue: BN scale/shift + bd + residual (x reloaded from global) ----
    const float rsv = rsqrtf(1.0f + 1e-5f);
    const int o0 = wrp * 8;
    const int jA = 2*lane, jB = 2*lane + 64;
    #pragma unroll
    for (int oo = 0; oo < 8; oo++) {
        int o = o0 + oo;
        float sc = gamma[o] * rsv;
        float bi = beta[o] + (bd[o] + bd[64 + o] + bd[128 + o]) * sc;
        u64 sc2 = splat2(sc), bi2 = splat2(bi);

        u64 y0 = *(const u64*)&yout[o*130 + jA];
        u64 y1 = *(const u64*)&yout[o*130 + jB];
        u64 r0 = bi2, r1 = bi2;
        fma2(r0, y0, sc2);
        fma2(r1, y1, sc2);
        r0 = add2(r0, *(const u64*)&x[xbase + (long)o*TV_ + jA]);
        r1 = add2(r1, *(const u64*)&x[xbase + (long)o*TV_ + jB]);

        *(u64*)&out[xbase + (long)o*TV_ + jA] = r0;
        *(u64*)&out[xbase + (long)o*TV_ + jB] = r1;
    }
}

// ---------------------------------------------------------------------------
extern "C" void kernel_launch(void* const* d_in, const int* in_sizes, int n_in,
                              void* d_out, int out_size)
{
    const float* x     = (const float*)d_in[0];
    const float* Abase = (const float*)d_in[1];
    const float* PA    = (const float*)d_in[2];
    const float* Wa    = (const float*)d_in[3];
    const float* ba    = (const float*)d_in[4];
    const float* Wb    = (const float*)d_in[5];
    const float* bb    = (const float*)d_in[6];
    const float* Wd    = (const float*)d_in[7];
    const float* bd    = (const float*)d_in[8];
    const float* gamma = (const float*)d_in[9];
    const float* beta  = (const float*)d_in[10];
    float* out = (float*)d_out;

    cudaFuncSetAttribute(k1_att_partial, cudaFuncAttributeMaxDynamicSharedMemorySize, SMEM1_BYTES);
    cudaFuncSetAttribute(k3_out,        cudaFuncAttributeMaxDynamicSharedMemorySize, SMEM3_BYTES);

    k0_prep<<<1, 256>>>(Wa, Wb, Wd);

    dim3 g1(NCH, N_);
    k1_att_partial<<<g1, 256, SMEM1_BYTES>>>(x, ba, bb);

    k2_softmax<<<N_*S_, 256>>>(Abase, PA);

    dim3 g3(NCH3, N_);
    k3_out<<<g3, 256, SMEM3_BYTES>>>(x, bd, gamma, beta, out);
}

// round 17
// speedup vs baseline: 1.1967x; 1.1967x over previous
#include <cuda_runtime.h>

// Problem dims
#define N_   128
#define C_   64
#define T_   288
#define V_   16
#define S_   3
#define IC_  16
#define KCT  (IC_*T_)      // 4608
#define TV_  (T_*V_)       // 4608

// Kernel 1 tiling
#define TT1  8
#define NCH  (T_/TT1)      // 36
#define FS1  196           // k1 fa/fb i-stride (≡ 4 mod 32)
#define FT1  24            // k1 fa/fb tp-stride

// Kernel 3 tiling
#define TT3  8
#define NCH3 (T_/TT3)      // 36
#define RS3  132           // k3 xs row stride (≡ 4 mod 32)

// Scratch (no cudaMalloc allowed)
__device__ float g_partial[(long)N_*NCH*S_*V_*V_];   // [n][ch][s][v*16+w]
__device__ float g_att[(long)N_*S_*V_*V_];           // [n][s][v*16+w]
__device__ uint4 g_Wfrag[S_*4*8*32];                 // Wd tf32 B-frags [s][og][step][lane]
__device__ uint2 g_W1frag[S_*2*2*8*32];              // Wa/Wb tf32 B-frags [s][ab][nt][ks][lane]

typedef unsigned long long u64;

__device__ __forceinline__ u64 splat2(float x) {
    u64 r; asm("mov.b64 %0, {%1, %1};" : "=l"(r) : "f"(x)); return r;
}
__device__ __forceinline__ void fma2(u64& d, u64 a, u64 b) {
    asm("fma.rn.f32x2 %0, %1, %2, %0;" : "+l"(d) : "l"(a), "l"(b));
}
__device__ __forceinline__ u64 add2(u64 a, u64 b) {
    u64 r; asm("add.rn.f32x2 %0, %1, %2;" : "=l"(r) : "l"(a), "l"(b)); return r;
}
__device__ __forceinline__ unsigned cvt_tf32(float f) {
    unsigned r; asm("cvt.rna.tf32.f32 %0, %1;" : "=r"(r) : "f"(f)); return r;
}
__device__ __forceinline__ void mma_tf32(float* d, unsigned a0, unsigned a1,
                                         unsigned a2, unsigned a3,
                                         unsigned b0, unsigned b1) {
    asm("mma.sync.aligned.m16n8k8.row.col.f32.tf32.tf32.f32 "
        "{%0,%1,%2,%3}, {%4,%5,%6,%7}, {%8,%9}, {%0,%1,%2,%3};"
        : "+f"(d[0]), "+f"(d[1]), "+f"(d[2]), "+f"(d[3])
        : "r"(a0), "r"(a1), "r"(a2), "r"(a3), "r"(b0), "r"(b1));
}

// ---------------------------------------------------------------------------
// Kernel 0: pre-pack Wd and Wa/Wb into tf32 mma B-fragments.
// ---------------------------------------------------------------------------
extern "C" __global__ void k0_prep(const float* __restrict__ Wa,
                                   const float* __restrict__ Wb,
                                   const float* __restrict__ Wd)
{
    const int tid = threadIdx.x;
    for (int idx = tid; idx < S_*4*8*32; idx += 256) {
        int lane = idx & 31, step = (idx >> 5) & 7, og = (idx >> 8) & 3, s = idx >> 10;
        int o = og*16 + (lane >> 2);
        int c = step*8 + (lane & 3);
        uint4 v;
        v.x = cvt_tf32(Wd[(s*64 + o    )*64 + c    ]);
        v.y = cvt_tf32(Wd[(s*64 + o    )*64 + c + 4]);
        v.z = cvt_tf32(Wd[(s*64 + o + 8)*64 + c    ]);
        v.w = cvt_tf32(Wd[(s*64 + o + 8)*64 + c + 4]);
        g_Wfrag[idx] = v;
    }
    for (int idx = tid; idx < S_*2*2*8*32; idx += 256) {
        int lane = idx & 31, ks = (idx >> 5) & 7, nt = (idx >> 8) & 1,
            ab = (idx >> 9) & 1, s = idx >> 10;
        int i = nt*8 + (lane >> 2);
        int c = ks*8 + (lane & 3);
        const float* W = ab ? Wb : Wa;
        uint2 v;
        v.x = cvt_tf32(W[(s*16 + i)*64 + c    ]);
        v.y = cvt_tf32(W[(s*16 + i)*64 + c + 4]);
        g_W1frag[idx] = v;
    }
}

// ---------------------------------------------------------------------------
// Kernel 1: att logit partials, tf32 mma. Grid (NCH, N), 256 threads, occ 3.
// A-fragments loaded directly from global x (hoisted across all 3 s).
// ---------------------------------------------------------------------------
#define SM1_FA   0
#define SM1_FB   (16*FS1)                    // 3136
#define SM1_ATTP (32*FS1)                    // 6272
#define SMEM1_BYTES ((32*FS1 + 8*256)*4)     // 33280 B

extern "C" __global__ void __launch_bounds__(256, 3)
k1_att_partial(const float* __restrict__ x,
               const float* __restrict__ ba, const float* __restrict__ bb)
{
    extern __shared__ float sm[];
    unsigned* fau = (unsigned*)(sm + SM1_FA);
    unsigned* fbu = (unsigned*)(sm + SM1_FB);
    float* attp = sm + SM1_ATTP;                // [8][256]

    const int ch  = blockIdx.x;
    const int n   = blockIdx.y;
    const int tid = threadIdx.x;
    const int lane = tid & 31, wrp = tid >> 5;
    const int lg = lane >> 2, l4 = lane & 3;
    const int j0p1 = wrp * 16;

    const long xbase = (long)n*C_*TV_ + (long)(ch*TT1)*V_;
    const float* xg = x + xbase;

    // Hoisted phase-1 A-frags: a = x[(ks*8 + l4 (+4))*TV + j0p1 + lg (+8)]
    unsigned af[8][4];
    #pragma unroll
    for (int ks = 0; ks < 8; ks++) {
        const float* r0p = &xg[(long)(ks*8 + l4    )*TV_ + j0p1 + lg];
        const float* r1p = &xg[(long)(ks*8 + l4 + 4)*TV_ + j0p1 + lg];
        af[ks][0] = cvt_tf32(__ldg(r0p));
        af[ks][1] = cvt_tf32(__ldg(r0p + 8));
        af[ks][2] = cvt_tf32(__ldg(r1p));
        af[ks][3] = cvt_tf32(__ldg(r1p + 8));
    }

    for (int s = 0; s < S_; s++) {
        // ---- phase 1: fa^T/fb^T via mma; warp owns j-tile [wrp*16, +16) ----
        {
            float dA[2][4], dB[2][4];
            #pragma unroll
            for (int nt = 0; nt < 2; nt++)
                #pragma unroll
                for (int r = 0; r < 4; r++) { dA[nt][r] = 0.f; dB[nt][r] = 0.f; }

            const uint2* wfa = &g_W1frag[((s*2 + 0)*2)*8*32 + lane];
            const uint2* wfb = &g_W1frag[((s*2 + 1)*2)*8*32 + lane];
            #pragma unroll
            for (int ks = 0; ks < 8; ks++) {
                uint2 bA0 = wfa[(0*8 + ks)*32];
                uint2 bA1 = wfa[(1*8 + ks)*32];
                uint2 bB0 = wfb[(0*8 + ks)*32];
                uint2 bB1 = wfb[(1*8 + ks)*32];
                mma_tf32(dA[0], af[ks][0], af[ks][1], af[ks][2], af[ks][3], bA0.x, bA0.y);
                mma_tf32(dA[1], af[ks][0], af[ks][1], af[ks][2], af[ks][3], bA1.x, bA1.y);
                mma_tf32(dB[0], af[ks][0], af[ks][1], af[ks][2], af[ks][3], bB0.x, bB0.y);
                mma_tf32(dB[1], af[ks][0], af[ks][1], af[ks][2], af[ks][3], bB1.x, bB1.y);
            }
            #pragma unroll
            for (int nt = 0; nt < 2; nt++) {
                int ii0 = nt*8 + 2*l4;
                float ba0 = __ldg(&ba[s*16 + ii0]), ba1 = __ldg(&ba[s*16 + ii0 + 1]);
                float bb0 = __ldg(&bb[s*16 + ii0]), bb1 = __ldg(&bb[s*16 + ii0 + 1]);
                int base0 =  ii0     *FS1 + wrp*FT1;
                int base1 = (ii0 + 1)*FS1 + wrp*FT1;
                fau[base0 + lg    ] = cvt_tf32(dA[nt][0] + ba0);
                fau[base1 + lg    ] = cvt_tf32(dA[nt][1] + ba1);
                fau[base0 + lg + 8] = cvt_tf32(dA[nt][2] + ba0);
                fau[base1 + lg + 8] = cvt_tf32(dA[nt][3] + ba1);
                fbu[base0 + lg    ] = cvt_tf32(dB[nt][0] + bb0);
                fbu[base1 + lg    ] = cvt_tf32(dB[nt][1] + bb1);
                fbu[base0 + lg + 8] = cvt_tf32(dB[nt][2] + bb0);
                fbu[base1 + lg + 8] = cvt_tf32(dB[nt][3] + bb1);
            }
        }
        __syncthreads();

        // ---- phase 2: att[v,w] partials via mma; warp owns i in {2w, 2w+1} ----
        {
            float p[2][4];
            #pragma unroll
            for (int nt = 0; nt < 2; nt++)
                #pragma unroll
                for (int r = 0; r < 4; r++) p[nt][r] = 0.f;

            #pragma unroll
            for (int t = 0; t < 2; t++) {
                int kk = wrp*2 + t;
                int ab = kk*FS1 + l4*FT1;
                unsigned a0 = fau[ab                  + lg    ];
                unsigned a1 = fau[ab                  + lg + 8];
                unsigned a2 = fau[kk*FS1 + (l4+4)*FT1 + lg    ];
                unsigned a3 = fau[kk*FS1 + (l4+4)*FT1 + lg + 8];
                #pragma unroll
                for (int nt = 0; nt < 2; nt++) {
                    unsigned b0 = fbu[ab                  + nt*8 + lg];
                    unsigned b1 = fbu[kk*FS1 + (l4+4)*FT1 + nt*8 + lg];
                    mma_tf32(p[nt], a0, a1, a2, a3, b0, b1);
                }
            }
            float* ap = &attp[wrp*256];
            #pragma unroll
            for (int nt = 0; nt < 2; nt++) {
                int w0 = nt*8 + 2*l4;
                ap[ lg     *16 + w0    ] = p[nt][0];
                ap[ lg     *16 + w0 + 1] = p[nt][1];
                ap[(lg + 8)*16 + w0    ] = p[nt][2];
                ap[(lg + 8)*16 + w0 + 1] = p[nt][3];
            }
        }
        __syncthreads();

        float red = 0.f;
        #pragma unroll
        for (int w = 0; w < 8; w++) red += attp[w*256 + tid];
        g_partial[(((long)n*NCH + ch)*S_ + s)*256 + tid] = red;
    }
}

// ---------------------------------------------------------------------------
// Kernel 2: reduce chunks, /K, softmax over v, + (A_base + PA).
// ---------------------------------------------------------------------------
extern "C" __global__ void k2_softmax(const float* __restrict__ Abase,
                                      const float* __restrict__ PA)
{
    const int b = blockIdx.x;          // n*3 + s
    const int n = b / S_, s = b % S_;
    const int tid = threadIdx.x;       // v*16 + w
    const int w = tid & 15;

    __shared__ float sv[256];
    __shared__ float se[256];

    float sum = 0.f;
    const float* p = &g_partial[((long)n*NCH)*S_*256 + s*256 + tid];
    for (int chv = 0; chv < NCH; chv++) sum += p[(long)chv * (S_*256)];
    float val = sum * (1.0f / (float)KCT);

    sv[tid] = val;
    __syncthreads();
    float m = -1e30f;
    #pragma unroll
    for (int vv = 0; vv < 16; vv++) m = fmaxf(m, sv[vv*16 + w]);
    float e = expf(val - m);
    se[tid] = e;
    __syncthreads();
    float ss = 0.f;
    #pragma unroll
    for (int vv = 0; vv < 16; vv++) ss += se[vv*16 + w];

    float a = e / ss + Abase[s*256 + tid] + PA[s*256 + tid];
    g_att[(long)b*256 + tid] = a;
}

// ---------------------------------------------------------------------------
// Kernel 3: fused z^T+y per warp, barrier-free mainloop (R11/R15 mapping,
// occ 3). Chain-shortened: z-mma split into two independent accumulators,
// and the z->y operand handoff passes raw fp32 bits (HW tf32 truncation)
// instead of cvt.rna — removes one HMMA latency + 4 dependent ALU ops from
// every step's critical path.
// Grid (NCH3, N), 256 threads, smem 36KB.
// ---------------------------------------------------------------------------
#define SM3_ATT  (64*RS3)                     // 8448
#define SMEM3_BYTES ((64*RS3 + S_*256)*4)     // 36864 B

extern "C" __global__ void __launch_bounds__(256, 3)
k3_out(const float* __restrict__ x,
       const float* __restrict__ bd, const float* __restrict__ gamma,
       const float* __restrict__ beta, float* __restrict__ out)
{
    extern __shared__ float sm[];
    unsigned* xsu   = (unsigned*)sm;           // [64][RS3] tf32 bits
    unsigned* attsu = xsu + SM3_ATT;           // [s][v][w] tf32 bits
    float* yout = sm;                          // overlays xs after mainloop

    const int ch  = blockIdx.x;
    const int n   = blockIdx.y;
    const int tid = threadIdx.x;
    const int lane = tid & 31, wrp = tid >> 5;
    const int lg = lane >> 2, l4 = lane & 3;
    const int plg = (lg >> 1) + ((lg & 1) << 2);   // pi(lg)

    const long xbase = (long)n*C_*TV_ + (long)(ch*TT3)*V_;
    for (int idx = tid; idx < 2048; idx += 256) {
        int c = idx >> 5, jp = (idx & 31)*4;
        float4 xv = *(const float4*)&x[xbase + (long)c*TV_ + jp];
        uint4 t;
        t.x = cvt_tf32(xv.x); t.y = cvt_tf32(xv.y);
        t.z = cvt_tf32(xv.z); t.w = cvt_tf32(xv.w);
        *(uint4*)&xsu[c*RS3 + jp] = t;
    }
    for (int idx = tid; idx < S_*256; idx += 256)
        attsu[idx] = cvt_tf32(g_att[(long)n*S_*256 + idx]);
    __syncthreads();

    const int t16 = wrp * 16;    // this warp's j-tile base

    float acc[8][4];             // [o-group of 8][frag]
    #pragma unroll
    for (int g = 0; g < 8; g++)
        #pragma unroll
        for (int r = 0; r < 4; r++) acc[g][r] = 0.f;

    for (int s = 0; s < S_; s++) {
        // att^T A-frags for z^T-mma (K = v, 2 ksteps)
        unsigned aA[2][4];
        const unsigned* ap = attsu + s*256;
        #pragma unroll
        for (int ks = 0; ks < 2; ks++) {
            aA[ks][0] = ap[(ks*8 + l4    )*16 + lg    ];
            aA[ks][1] = ap[(ks*8 + l4    )*16 + lg + 8];
            aA[ks][2] = ap[(ks*8 + l4 + 4)*16 + lg    ];
            aA[ks][3] = ap[(ks*8 + l4 + 4)*16 + lg + 8];
        }
        const uint4* wfp = &g_Wfrag[s*4*256 + lane];
        #pragma unroll
        for (int step = 0; step < 8; step++) {
            // z^T-mma: two INDEPENDENT accumulators (parallel HMMA), summed after
            int xb = (step*8 + plg)*RS3 + t16 + l4;   // conflict-free LDS
            float d0[4] = {0.f, 0.f, 0.f, 0.f};
            float d1[4] = {0.f, 0.f, 0.f, 0.f};
            mma_tf32(d0, aA[0][0], aA[0][1], aA[0][2], aA[0][3],
                     xsu[xb], xsu[xb + 4]);
            mma_tf32(d1, aA[1][0], aA[1][1], aA[1][2], aA[1][3],
                     xsu[xb + 8], xsu[xb + 12]);
            // z -> y operands: raw fp32 bits (HW truncates to tf32), no cvt
            unsigned y0 = __float_as_uint(d0[0] + d1[0]);
            unsigned y1 = __float_as_uint(d0[2] + d1[2]);
            unsigned y2 = __float_as_uint(d0[1] + d1[1]);
            unsigned y3 = __float_as_uint(d0[3] + d1[3]);
            // y-mma across all 4 Wd og-frags (8 n-groups)
            #pragma unroll
            for (int og = 0; og < 4; og++) {
                uint4 bfw = wfp[og*256 + step*32];    // LDG.128, L1-resident
                mma_tf32(acc[og*2    ], y0, y1, y2, y3, bfw.x, bfw.y);
                mma_tf32(acc[og*2 + 1], y0, y1, y2, y3, bfw.z, bfw.w);
            }
        }
    }
    __syncthreads();   // all xs reads done; yout overlays xs

    // ---- scatter y D-frags to yout as [o][130] ----
    #pragma unroll
    for (int g = 0; g < 8; g++) {
        int oc = g*8 + 2*l4;
        int jr = t16 + lg;
        yout[ oc     *130 + jr    ] = acc[g][0];
        yout[(oc + 1)*130 + jr    ] = acc[g][1];
        yout[ oc     *130 + jr + 8] = acc[g][2];
        yout[(oc + 1)*130 + jr + 8] = acc[g][3];
    }
    __syncthreads();

    // ---- epilogue: BN scale/shift + bd + residual (x reloaded from global) ----
    const float rsv = rsqrtf(1.0f + 1e-5f);
    const int o0 = wrp * 8;
    const int jA = 2*lane, jB = 2*lane + 64;
    #pragma unroll
    for (int oo = 0; oo < 8; oo++) {
        int o = o0 + oo;
        float sc = gamma[o] * rsv;
        float bi = beta[o] + (bd[o] + bd[64 + o] + bd[128 + o]) * sc;
        u64 sc2 = splat2(sc), bi2 = splat2(bi);

        u64 y0 = *(const u64*)&yout[o*130 + jA];
        u64 y1 = *(const u64*)&yout[o*130 + jB];
        u64 r0 = bi2, r1 = bi2;
        fma2(r0, y0, sc2);
        fma2(r1, y1, sc2);
        r0 = add2(r0, *(const u64*)&x[xbase + (long)o*TV_ + jA]);
        r1 = add2(r1, *(const u64*)&x[xbase + (long)o*TV_ + jB]);

        *(u64*)&out[xbase + (long)o*TV_ + jA] = r0;
        *(u64*)&out[xbase + (long)o*TV_ + jB] = r1;
    }
}

// ---------------------------------------------------------------------------
extern "C" void kernel_launch(void* const* d_in, const int* in_sizes, int n_in,
                              void* d_out, int out_size)
{
    const float* x     = (const float*)d_in[0];
    const float* Abase = (const float*)d_in[1];
    const float* PA    = (const float*)d_in[2];
    const float* Wa    = (const float*)d_in[3];
    const float* ba    = (const float*)d_in[4];
    const float* Wb    = (const float*)d_in[5];
    const float* bb    = (const float*)d_in[6];
    const float* Wd    = (const float*)d_in[7];
    const float* bd    = (const float*)d_in[8];
    const float* gamma = (const float*)d_in[9];
    const float* beta  = (const float*)d_in[10];
    float* out = (float*)d_out;

    cudaFuncSetAttribute(k1_att_partial, cudaFuncAttributeMaxDynamicSharedMemorySize, SMEM1_BYTES);
    cudaFuncSetAttribute(k3_out,        cudaFuncAttributeMaxDynamicSharedMemorySize, SMEM3_BYTES);

    k0_prep<<<1, 256>>>(Wa, Wb, Wd);

    dim3 g1(NCH, N_);
    k1_att_partial<<<g1, 256, SMEM1_BYTES>>>(x, ba, bb);

    k2_softmax<<<N_*S_, 256>>>(Abase, PA);

    dim3 g3(NCH3, N_);
    k3_out<<<g3, 256, SMEM3_BYTES>>>(x, bd, gamma, beta, out);
}